// round 1
// baseline (speedup 1.0000x reference)
#include <cuda_runtime.h>

// CapsuleLayer dynamic routing, fully fused, hat recomputed per pass (never materialized).
// B=256, IN_CAPS=1152, IN_DIM=8, NUM_CAPS=10, DIM_VEC=16, NUM_ROUTING=3.
//
// Pass structure (agreement is linear in v, so logits never stored):
//   pass0: c = softmax(bias)          -> s0 partials  -> squash -> v0, vsum=v0
//   pass1: c = softmax(bias+hat·v0)   -> s1 partials  -> squash -> v1, vsum+=v1
//   pass2: c = softmax(bias+hat·vsum) -> s2 partials  -> squash -> out

#define BATCH 256
#define IC 1152
#define ID 8
#define NC 10
#define DV 16
#define ICHUNK 64
#define NCHUNKS (IC / ICHUNK)   // 18
#define BB 4                    // batches per block
#define NBGRP (BATCH / BB)      // 64
#define NT 160                  // threads = NC*DV

// ---- scratch (device globals, no allocations) ----
__device__ float g_c0[IC * NC];                          // softmax(bias), i-only
__device__ float g_spart[NCHUNKS * BATCH * NC * DV];     // per-chunk s partials
__device__ float g_v[BATCH * NC * DV];                   // latest v
__device__ float g_vsum[BATCH * NC * DV];                // v0 (+ v1)

// ---------------------------------------------------------------------------
// c0 = softmax(bias[0, i, :]) over NC  (iteration 0 coupling, b-independent)
// ---------------------------------------------------------------------------
__global__ void c0_kernel(const float* __restrict__ bias) {
    int i = blockIdx.x * blockDim.x + threadIdx.x;
    if (i >= IC) return;
    float l[NC];
    float m = -1e30f;
#pragma unroll
    for (int j = 0; j < NC; ++j) { l[j] = bias[i * NC + j]; m = fmaxf(m, l[j]); }
    float den = 0.f;
#pragma unroll
    for (int j = 0; j < NC; ++j) { l[j] = __expf(l[j] - m); den += l[j]; }
    float rd = 1.f / den;
#pragma unroll
    for (int j = 0; j < NC; ++j) g_c0[i * NC + j] = l[j] * rd;
}

// ---------------------------------------------------------------------------
// Fused routing pass. Thread t = (j,d). Each block: BB batches x ICHUNK caps.
// hat[b,i,j,d] recomputed from x,W in registers each iteration.
// VSRC: 0 -> use precomputed g_c0 (iteration 0)
//       1 -> agreement against g_v   (iteration 1)
//       2 -> agreement against g_vsum (iteration 2, since logits are linear in v)
// ---------------------------------------------------------------------------
template <int VSRC>
__global__ __launch_bounds__(NT) void pass_kernel(
    const float* __restrict__ x,     // [B, IC, ID]
    const float* __restrict__ W,     // [IC, NC, ID, DV]
    const float* __restrict__ bias)  // [1, IC, NC]
{
    const int bgrp  = blockIdx.x;    // 0..63
    const int chunk = blockIdx.y;    // 0..17
    const int t = threadIdx.x;       // 0..159
    const int j = t >> 4;            // output capsule
    const int d = t & 15;            // vector dim
    const int b0 = bgrp * BB;

    __shared__ float sm_l[BB][16];   // logits (only [..][0..9] valid)
    __shared__ float sm_c[BB][16];   // coupling coefficients

    float vreg[BB];
    if (VSRC) {
        const float* vp = (VSRC == 1) ? g_v : g_vsum;
#pragma unroll
        for (int bb = 0; bb < BB; ++bb)
            vreg[bb] = vp[((b0 + bb) * NC + j) * DV + d];
    }

    float sacc[BB];
#pragma unroll
    for (int bb = 0; bb < BB; ++bb) sacc[bb] = 0.f;

    const int i0 = chunk * ICHUNK;
    for (int ii = 0; ii < ICHUNK; ++ii) {
        const int i = i0 + ii;

        // W[i, j, :, d] -> 8 registers (L2-resident, 5.9MB total)
        float wr[ID];
        const float* Wp = W + ((size_t)i * NC + j) * (ID * DV) + d;
#pragma unroll
        for (int e = 0; e < ID; ++e) wr[e] = __ldg(Wp + e * DV);

        // hat[bb] = x[b,i,:] . W[i,j,:,d]
        float hat[BB];
#pragma unroll
        for (int bb = 0; bb < BB; ++bb) {
            const float4* xp = (const float4*)(x + ((size_t)(b0 + bb) * IC + i) * ID);
            float4 x0 = __ldg(xp);
            float4 x1 = __ldg(xp + 1);
            float h = x0.x * wr[0];
            h = fmaf(x0.y, wr[1], h);
            h = fmaf(x0.z, wr[2], h);
            h = fmaf(x0.w, wr[3], h);
            h = fmaf(x1.x, wr[4], h);
            h = fmaf(x1.y, wr[5], h);
            h = fmaf(x1.z, wr[6], h);
            h = fmaf(x1.w, wr[7], h);
            hat[bb] = h;
        }

        if (VSRC) {
            float bi = 0.f;
            if (d == 0) bi = __ldg(&bias[i * NC + j]);

            // agreement a[b,j] = sum_d hat*v : 16-lane xor reduction
#pragma unroll
            for (int bb = 0; bb < BB; ++bb) {
                float a = hat[bb] * vreg[bb];
#pragma unroll
                for (int off = 8; off > 0; off >>= 1)
                    a += __shfl_xor_sync(0xffffffffu, a, off);
                if (d == 0) sm_l[bb][j] = a + bi;
            }
            __syncthreads();

            // softmax over NC=10 caps, one 16-lane group per batch (warps 0-1)
            if (t < BB * 16) {
                const int bb = t >> 4, jj = t & 15;
                float l = (jj < NC) ? sm_l[bb][jj] : -1e30f;
                float m = l;
#pragma unroll
                for (int off = 8; off > 0; off >>= 1)
                    m = fmaxf(m, __shfl_xor_sync(0xffffffffu, m, off));
                float e = (jj < NC) ? __expf(l - m) : 0.f;
                float den = e;
#pragma unroll
                for (int off = 8; off > 0; off >>= 1)
                    den += __shfl_xor_sync(0xffffffffu, den, off);
                sm_c[bb][jj] = __fdividef(e, den);
            }
            __syncthreads();

#pragma unroll
            for (int bb = 0; bb < BB; ++bb)
                sacc[bb] = fmaf(sm_c[bb][j], hat[bb], sacc[bb]);
        } else {
            const float cj = g_c0[i * NC + j];
#pragma unroll
            for (int bb = 0; bb < BB; ++bb)
                sacc[bb] = fmaf(cj, hat[bb], sacc[bb]);
        }
    }

    // deterministic two-stage reduction: write per-chunk partials
#pragma unroll
    for (int bb = 0; bb < BB; ++bb)
        g_spart[((size_t)chunk * BATCH + (b0 + bb)) * (NC * DV) + t] = sacc[bb];
}

// ---------------------------------------------------------------------------
// Reduce chunk partials and squash. Thread t = (b*NC+j)*DV + d.
// MODE 0: v -> g_v, g_vsum = v      (after pass0)
// MODE 1: v -> g_v, g_vsum += v     (after pass1)
// MODE 2: v -> out                  (final)
// ---------------------------------------------------------------------------
template <int MODE>
__global__ void squash_kernel(float* __restrict__ out) {
    const int t = blockIdx.x * blockDim.x + threadIdx.x;  // < 40960
    float s = 0.f;
#pragma unroll
    for (int c = 0; c < NCHUNKS; ++c)
        s += g_spart[(size_t)c * (BATCH * NC * DV) + t];
    float s2 = s * s;
#pragma unroll
    for (int off = 8; off > 0; off >>= 1)
        s2 += __shfl_xor_sync(0xffffffffu, s2, off);   // ||s||^2 over d (16 lanes)
    const float scale = s2 / (1.f + s2) * rsqrtf(s2);
    const float v = scale * s;
    if (MODE == 2) {
        out[t] = v;
    } else {
        g_v[t] = v;
        if (MODE == 0) g_vsum[t] = v;
        else           g_vsum[t] += v;
    }
}

// ---------------------------------------------------------------------------
extern "C" void kernel_launch(void* const* d_in, const int* in_sizes, int n_in,
                              void* d_out, int out_size) {
    const float* x    = (const float*)d_in[0];  // [256, 1152, 8]
    const float* W    = (const float*)d_in[1];  // [1152, 10, 8, 16]
    const float* bias = (const float*)d_in[2];  // [1, 1152, 10]
    float* out = (float*)d_out;                 // [256, 10, 16]

    dim3 pg(NBGRP, NCHUNKS);
    const int sq_blocks = (BATCH * NC * DV) / 256;  // 160

    c0_kernel<<<(IC + 127) / 128, 128>>>(bias);
    pass_kernel<0><<<pg, NT>>>(x, W, bias);
    squash_kernel<0><<<sq_blocks, 256>>>(nullptr);
    pass_kernel<1><<<pg, NT>>>(x, W, bias);
    squash_kernel<1><<<sq_blocks, 256>>>(nullptr);
    pass_kernel<2><<<pg, NT>>>(x, W, bias);
    squash_kernel<2><<<sq_blocks, 256>>>(out);
}

// round 2
// speedup vs baseline: 2.0081x; 2.0081x over previous
#include <cuda_runtime.h>

// CapsuleLayer dynamic routing, fully fused, barrier-free warp-local passes.
// B=256, IN_CAPS=1152, IN_DIM=8, NUM_CAPS=10, DIM_VEC=16, NUM_ROUTING=3.
//
// pass0: c = softmax(bias)          -> s0 partials -> squash -> v0, vsum=v0
// pass1: c = softmax(bias+hat.v0)   -> s1 partials -> squash -> v1, vsum+=v1
// pass2: c = softmax(bias+hat.vsum) -> s2 partials -> squash -> out
// (agreement is linear in v, so logits are never materialized)
//
// Warp layout: lane = 16*h + d (h in {0,1}, d in [0,16)).
// Each lane owns 5 caps j = h+2k. Agreement = 4-level shfl_xor over d;
// softmax over 10 caps = per-lane max/sum over 5 + one shfl_xor(16).
// Zero __syncthreads in the passes.

#define BATCH 256
#define IC 1152
#define ID 8
#define NC 10
#define DV 16
#define BB 4                    // batches per warp
#define NBGRP (BATCH / BB)      // 64
#define ICHUNK 16
#define NCHUNKS (IC / ICHUNK)   // 72
#define JPL 5                   // caps per lane
#define WPB 8                   // warps per block (share i-chunk -> L1 W reuse)

// ---- scratch (device globals, no allocations) ----
__device__ float g_Wt[IC * NC * DV * ID];                 // W transposed: [i,j,d,e]
__device__ float g_c0[IC * NC];                           // softmax(bias), i-only
__device__ float g_spart[NCHUNKS * BATCH * NC * DV];      // per-chunk s partials
__device__ float g_v[BATCH * NC * DV];                    // latest v
__device__ float g_vsum[BATCH * NC * DV];                 // v0 (+ v1)

// ---------------------------------------------------------------------------
// W[i,j,e,d] -> g_Wt[i,j,d,e]  (so a lane's 8 e-values are 2 float4 loads)
// ---------------------------------------------------------------------------
__global__ void wt_kernel(const float* __restrict__ W) {
    int t = blockIdx.x * blockDim.x + threadIdx.x;   // over IC*NC*DV = 184320
    if (t >= IC * NC * DV) return;
    int d = t & (DV - 1);
    int ij = t >> 4;                                  // i*NC + j
    const float* src = W + (size_t)ij * (ID * DV) + d;
    float4 lo, hi;
    lo.x = __ldg(src + 0 * DV); lo.y = __ldg(src + 1 * DV);
    lo.z = __ldg(src + 2 * DV); lo.w = __ldg(src + 3 * DV);
    hi.x = __ldg(src + 4 * DV); hi.y = __ldg(src + 5 * DV);
    hi.z = __ldg(src + 6 * DV); hi.w = __ldg(src + 7 * DV);
    float4* dst = (float4*)(g_Wt + (size_t)t * ID);
    dst[0] = lo; dst[1] = hi;
}

// ---------------------------------------------------------------------------
// c0 = softmax(bias[0,i,:]) over NC  (iteration-0 coupling, b-independent)
// ---------------------------------------------------------------------------
__global__ void c0_kernel(const float* __restrict__ bias) {
    int i = blockIdx.x * blockDim.x + threadIdx.x;
    if (i >= IC) return;
    float l[NC];
    float m = -1e30f;
#pragma unroll
    for (int j = 0; j < NC; ++j) { l[j] = bias[i * NC + j]; m = fmaxf(m, l[j]); }
    float den = 0.f;
#pragma unroll
    for (int j = 0; j < NC; ++j) { l[j] = __expf(l[j] - m); den += l[j]; }
    float rd = __fdividef(1.f, den);
#pragma unroll
    for (int j = 0; j < NC; ++j) g_c0[i * NC + j] = l[j] * rd;
}

// ---------------------------------------------------------------------------
// Fused routing pass, barrier-free. Each warp: (bgroup of BB batches, i-chunk).
// VSRC: 0 -> g_c0;  1 -> agreement vs g_v;  2 -> agreement vs g_vsum
// ---------------------------------------------------------------------------
template <int VSRC>
__global__ __launch_bounds__(WPB * 32, 2) void pass_kernel(
    const float* __restrict__ x,     // [B, IC, ID]
    const float* __restrict__ bias)  // [1, IC, NC]
{
    const int lane = threadIdx.x & 31;
    const int w    = threadIdx.x >> 5;
    const int d    = lane & 15;
    const int h    = lane >> 4;              // 0 or 1
    const int chunk = blockIdx.x;            // 0..NCHUNKS-1 (shared by all warps in block)
    const int bgrp  = blockIdx.y * WPB + w;  // 0..63
    const int b0    = bgrp * BB;

    // v (or vsum) for this lane's 5 caps x 4 batches
    float vreg[JPL][BB];
    if (VSRC) {
        const float* vp = (VSRC == 1) ? g_v : g_vsum;
#pragma unroll
        for (int k = 0; k < JPL; ++k) {
            const int j = h + 2 * k;
#pragma unroll
            for (int bb = 0; bb < BB; ++bb)
                vreg[k][bb] = vp[(b0 + bb) * (NC * DV) + j * DV + d];
        }
    }

    float sacc[JPL][BB];
#pragma unroll
    for (int k = 0; k < JPL; ++k)
#pragma unroll
        for (int bb = 0; bb < BB; ++bb) sacc[k][bb] = 0.f;

    const int i0 = chunk * ICHUNK;
    for (int ii = 0; ii < ICHUNK; ++ii) {
        const int i = i0 + ii;

        // x[b, i, 0..7] (uniform-address broadcast loads)
        float4 xa[BB], xb[BB];
#pragma unroll
        for (int bb = 0; bb < BB; ++bb) {
            const float4* xp = (const float4*)(x + ((size_t)(b0 + bb) * IC + i) * ID);
            xa[bb] = __ldg(xp);
            xb[bb] = __ldg(xp + 1);
        }

        // hat[k][bb] = x[b,i,:] . W[i,j,:,d]   (W_t: 2 x LDG.128 per cap)
        float hat[JPL][BB];
#pragma unroll
        for (int k = 0; k < JPL; ++k) {
            const int j = h + 2 * k;
            const float4* wp = (const float4*)(g_Wt + (((size_t)i * NC + j) * DV + d) * ID);
            const float4 w0 = __ldg(wp);
            const float4 w1 = __ldg(wp + 1);
#pragma unroll
            for (int bb = 0; bb < BB; ++bb) {
                float hv = xa[bb].x * w0.x;
                hv = fmaf(xa[bb].y, w0.y, hv);
                hv = fmaf(xa[bb].z, w0.z, hv);
                hv = fmaf(xa[bb].w, w0.w, hv);
                hv = fmaf(xb[bb].x, w1.x, hv);
                hv = fmaf(xb[bb].y, w1.y, hv);
                hv = fmaf(xb[bb].z, w1.z, hv);
                hv = fmaf(xb[bb].w, w1.w, hv);
                hat[k][bb] = hv;
            }
        }

        if (VSRC) {
            float bs[JPL];
#pragma unroll
            for (int k = 0; k < JPL; ++k)
                bs[k] = __ldg(&bias[i * NC + h + 2 * k]);

#pragma unroll
            for (int bb = 0; bb < BB; ++bb) {
                // agreement a[j] = sum_d hat*v : 4-level butterfly over d (in 16-group)
                float a[JPL];
#pragma unroll
                for (int k = 0; k < JPL; ++k) a[k] = hat[k][bb] * vreg[k][bb];
#pragma unroll
                for (int off = 1; off <= 8; off <<= 1) {
#pragma unroll
                    for (int k = 0; k < JPL; ++k)
                        a[k] += __shfl_xor_sync(0xffffffffu, a[k], off);
                }
#pragma unroll
                for (int k = 0; k < JPL; ++k) a[k] += bs[k];

                // softmax over all 10 caps: local 5 + cross-half exchange
                float m = a[0];
#pragma unroll
                for (int k = 1; k < JPL; ++k) m = fmaxf(m, a[k]);
                m = fmaxf(m, __shfl_xor_sync(0xffffffffu, m, 16));
                float e[JPL];
                float den = 0.f;
#pragma unroll
                for (int k = 0; k < JPL; ++k) { e[k] = __expf(a[k] - m); den += e[k]; }
                den += __shfl_xor_sync(0xffffffffu, den, 16);
                const float rden = __fdividef(1.f, den);
#pragma unroll
                for (int k = 0; k < JPL; ++k)
                    sacc[k][bb] = fmaf(e[k] * rden, hat[k][bb], sacc[k][bb]);
            }
        } else {
            float c[JPL];
#pragma unroll
            for (int k = 0; k < JPL; ++k)
                c[k] = g_c0[i * NC + h + 2 * k];
#pragma unroll
            for (int k = 0; k < JPL; ++k)
#pragma unroll
                for (int bb = 0; bb < BB; ++bb)
                    sacc[k][bb] = fmaf(c[k], hat[k][bb], sacc[k][bb]);
        }
    }

    // deterministic two-stage reduction: per-chunk partials
#pragma unroll
    for (int k = 0; k < JPL; ++k) {
        const int t_out = (h + 2 * k) * DV + d;
#pragma unroll
        for (int bb = 0; bb < BB; ++bb)
            g_spart[((size_t)chunk * BATCH + (b0 + bb)) * (NC * DV) + t_out] = sacc[k][bb];
    }
}

// ---------------------------------------------------------------------------
// Reduce chunk partials + squash. Thread t = (b*NC+j)*DV + d.
// MODE 0: v -> g_v, g_vsum = v ; MODE 1: v -> g_v, g_vsum += v ; MODE 2: -> out
// ---------------------------------------------------------------------------
template <int MODE>
__global__ void squash_kernel(float* __restrict__ out) {
    const int t = blockIdx.x * blockDim.x + threadIdx.x;   // < 40960
    float s = 0.f;
#pragma unroll
    for (int c = 0; c < NCHUNKS; ++c)
        s += g_spart[(size_t)c * (BATCH * NC * DV) + t];
    float s2 = s * s;
#pragma unroll
    for (int off = 8; off > 0; off >>= 1)
        s2 += __shfl_xor_sync(0xffffffffu, s2, off);       // ||s||^2 over d (16 lanes)
    const float scale = s2 / (1.f + s2) * rsqrtf(s2);
    const float v = scale * s;
    if (MODE == 2) {
        out[t] = v;
    } else {
        g_v[t] = v;
        if (MODE == 0) g_vsum[t] = v;
        else           g_vsum[t] += v;
    }
}

// ---------------------------------------------------------------------------
extern "C" void kernel_launch(void* const* d_in, const int* in_sizes, int n_in,
                              void* d_out, int out_size) {
    const float* x    = (const float*)d_in[0];  // [256, 1152, 8]
    const float* W    = (const float*)d_in[1];  // [1152, 10, 8, 16]
    const float* bias = (const float*)d_in[2];  // [1, 1152, 10]
    float* out = (float*)d_out;                 // [256, 10, 16]

    dim3 pg(NCHUNKS, NBGRP / WPB);              // (72, 8)
    const int sq_blocks = (BATCH * NC * DV) / 256;  // 160

    wt_kernel<<<(IC * NC * DV + 255) / 256, 256>>>(W);
    c0_kernel<<<(IC + 127) / 128, 128>>>(bias);
    pass_kernel<0><<<pg, WPB * 32>>>(x, bias);
    squash_kernel<0><<<sq_blocks, 256>>>(nullptr);
    pass_kernel<1><<<pg, WPB * 32>>>(x, bias);
    squash_kernel<1><<<sq_blocks, 256>>>(nullptr);
    pass_kernel<2><<<pg, WPB * 32>>>(x, bias);
    squash_kernel<2><<<sq_blocks, 256>>>(out);
}